// round 1
// baseline (speedup 1.0000x reference)
#include <cuda_runtime.h>
#include <math.h>

#define FULL 0xffffffffu

// Deterministic scratch (no device-side allocation allowed).
__device__ float g_ds3[4 * 256 * 169];
__device__ float g_ds4[4 * 512 * 25];
__device__ float g_s1_3[4 * 256];
__device__ float g_s1_4[4 * 512];

// ---------------------------------------------------------------------------
// Patch kernel: one warp per patch-pair.
//   lanes 0-15  : ref matrix P_r  (lane r holds row r, 16 registers)
//   lanes 16-31 : dist matrix P_d
// Matrix (after reference's swapaxes): P[m][n] = x[ph*4 + n][pw*4 + m]
// => lane r, register c:  v[c] = x[ph*4 + c][pw*4 + r]   (coalesced per c)
// One-sided Jacobi orthogonalizes columns; column j converges to sigma_j*u_j.
// ---------------------------------------------------------------------------
template <int LAYER, int C, int H, int W, int NH, int NW, int NSWEEP>
__global__ __launch_bounds__(256) void patch_kernel(const float* __restrict__ ref,
                                                    const float* __restrict__ dist) {
    constexpr int NP = NH * NW;
    const int warpId = (blockIdx.x * blockDim.x + threadIdx.x) >> 5;
    const int lane = threadIdx.x & 31;
    const int sub = lane >> 4;   // 0 = ref, 1 = dist
    const int r = lane & 15;     // matrix row owned by this lane

    float* ds_out = (LAYER == 3) ? g_ds3 : g_ds4;

    int a = warpId / (C * NP);
    int rem = warpId - a * (C * NP);
    int b = rem / NP;
    int p = rem - b * NP;
    int ph = p / NW;
    int pw = p - ph * NW;

    const float* src = sub ? dist : ref;
    const float* base = src + (((size_t)(a * C + b)) * H + (size_t)(ph * 4)) * W + (pw * 4 + r);

    float v[16];
#pragma unroll
    for (int c = 0; c < 16; c++) v[c] = base[(size_t)c * W];

    // ---- one-sided Jacobi sweeps (cyclic pair order, fully unrolled body) ----
#pragma unroll 1
    for (int sw = 0; sw < NSWEEP; sw++) {
#pragma unroll
        for (int i = 0; i < 15; i++) {
#pragma unroll
            for (int j = i + 1; j < 16; j++) {
                float app = v[i] * v[i];
                float aqq = v[j] * v[j];
                float apq = v[i] * v[j];
#pragma unroll
                for (int o = 1; o < 16; o <<= 1) {
                    app += __shfl_xor_sync(FULL, app, o);
                    aqq += __shfl_xor_sync(FULL, aqq, o);
                    apq += __shfl_xor_sync(FULL, apq, o);
                }
                // Uniform within each 16-lane half (butterfly is bitwise symmetric).
                if (apq * apq > 1e-30f) {
                    float tau = __fdividef(aqq - app, 2.0f * apq);
                    float g = fmaf(tau, tau, 1.0f);
                    float sq = g * rsqrtf(g);              // ~sqrt(1+tau^2)
                    float t = __fdividef(1.0f, fabsf(tau) + sq);
                    t = copysignf(t, tau);
                    float cc = rsqrtf(fmaf(t, t, 1.0f));
                    float ss = t * cc;
                    float vi = v[i], vj = v[j];
                    v[i] = fmaf(cc, vi, -ss * vj);
                    v[j] = fmaf(ss, vi, cc * vj);
                }
            }
        }
    }

    // ---- column norms via transposing reduction: lane j ends with ||col j||^2 ----
    float acc[16];
#pragma unroll
    for (int j = 0; j < 16; j++) acc[j] = v[j] * v[j];

    float a8[8];
#pragma unroll
    for (int m = 0; m < 8; m++) {
        bool hi = (r & 1);
        float send = hi ? acc[2 * m] : acc[2 * m + 1];
        float recv = __shfl_xor_sync(FULL, send, 1);
        a8[m] = (hi ? acc[2 * m + 1] : acc[2 * m]) + recv;
    }
    float a4v[4];
#pragma unroll
    for (int m = 0; m < 4; m++) {
        bool hi = (r & 2);
        float send = hi ? a8[2 * m] : a8[2 * m + 1];
        float recv = __shfl_xor_sync(FULL, send, 2);
        a4v[m] = (hi ? a8[2 * m + 1] : a8[2 * m]) + recv;
    }
    float a2v[2];
#pragma unroll
    for (int m = 0; m < 2; m++) {
        bool hi = (r & 4);
        float send = hi ? a4v[2 * m] : a4v[2 * m + 1];
        float recv = __shfl_xor_sync(FULL, send, 4);
        a2v[m] = (hi ? a4v[2 * m + 1] : a4v[2 * m]) + recv;
    }
    float a1;
    {
        bool hi = (r & 8);
        float send = hi ? a2v[0] : a2v[1];
        float recv = __shfl_xor_sync(FULL, send, 8);
        a1 = (hi ? a2v[1] : a2v[0]) + recv;
    }
    float s_local = sqrtf(a1);   // sigma of column r (held by lane r)

    // ---- broadcast sigmas, compute descending ranks (ties broken by index) ----
    const int base_lane = lane & 16;
    float s_all[16];
#pragma unroll
    for (int k = 0; k < 16; k++) s_all[k] = __shfl_sync(FULL, s_local, base_lane + k);
    int rk = 0;
#pragma unroll
    for (int k = 0; k < 16; k++)
        rk += (int)((s_all[k] > s_local) || (s_all[k] == s_local && k < r));
    int rank_all[16];
#pragma unroll
    for (int k = 0; k < 16; k++) rank_all[k] = __shfl_sync(FULL, rk, base_lane + k);

    // ---- stage sorted, normalized U and sorted sigmas in shared memory ----
    __shared__ float Ush[8][2][16][16];   // [warp][sub][sorted_col][row]
    __shared__ float Ssh[8][2][16];       // [warp][sub][sorted_col]
    const int wl = threadIdx.x >> 5;
    Ssh[wl][sub][rk] = s_local;
#pragma unroll
    for (int j = 0; j < 16; j++) {
        Ush[wl][sub][rank_all[j]][r] = v[j] * __fdividef(1.0f, s_all[j] + 1e-30f);
    }
    __syncwarp();

    // ---- combine ref/dist: u_rd per row, diff of sorted sigmas ----
    float urd = 0.0f;
#pragma unroll
    for (int i = 0; i < 16; i++)
        urd += fabsf(Ush[wl][0][i][r] * Ush[wl][1][i][r]);
    float d = Ssh[wl][0][r] - Ssh[wl][1][r];

    float sd = d * d;
    float su = urd;
    float sq2 = urd * urd;
#pragma unroll
    for (int o = 1; o < 16; o <<= 1) {
        sd += __shfl_xor_sync(FULL, sd, o);
        su += __shfl_xor_sync(FULL, su, o);
        sq2 += __shfl_xor_sync(FULL, sq2, o);
    }
    if (lane == 0) {
        float mean = su * (1.0f / 16.0f);
        float var = (sq2 - su * su * (1.0f / 16.0f)) * (1.0f / 15.0f);  // ddof=1
        float wt = sqrtf(fmaxf(var, 0.0f)) * __fdividef(1.0f, mean + 1e-9f);
        ds_out[warpId] = sd * wt;
    }
}

// ---------------------------------------------------------------------------
// Per-channel global means -> s1 term.
// ---------------------------------------------------------------------------
template <int LAYER, int HW>
__global__ __launch_bounds__(256) void mean_kernel(const float* __restrict__ ref,
                                                   const float* __restrict__ dist) {
    float* s1out = (LAYER == 3) ? g_s1_3 : g_s1_4;
    const int ac = blockIdx.x;
    const float* rp = ref + (size_t)ac * HW;
    const float* dp = dist + (size_t)ac * HW;
    float sr = 0.0f, sdd = 0.0f;
    for (int i = threadIdx.x; i < HW; i += 256) {
        sr += rp[i];
        sdd += dp[i];
    }
    __shared__ float shr[256], shd[256];
    shr[threadIdx.x] = sr;
    shd[threadIdx.x] = sdd;
    __syncthreads();
    for (int o = 128; o > 0; o >>= 1) {
        if (threadIdx.x < o) {
            shr[threadIdx.x] += shr[threadIdx.x + o];
            shd[threadIdx.x] += shd[threadIdx.x + o];
        }
        __syncthreads();
    }
    if (threadIdx.x == 0) {
        float ym = shr[0] * (1.0f / HW);   // ref mean
        float xm = shd[0] * (1.0f / HW);   // dist mean
        float s1 = (2.0f * xm * ym + 1e-6f) / (xm * xm + ym * ym + 1e-6f);
        s1out[ac] = s1;
    }
}

// ---------------------------------------------------------------------------
// Final deterministic reduction: block a computes out[a].
// ---------------------------------------------------------------------------
__global__ __launch_bounds__(256) void final_kernel(float* __restrict__ out) {
    const int a = blockIdx.x;
    const int t = threadIdx.x;
    __shared__ float sh[256];

    auto block_reduce = [&](float vloc) -> float {
        sh[t] = vloc;
        __syncthreads();
        for (int o = 128; o > 0; o >>= 1) {
            if (t < o) sh[t] += sh[t + o];
            __syncthreads();
        }
        float res = sh[0];
        __syncthreads();
        return res;
    };

    float s = 0.0f;
    for (int i = t; i < 256 * 169; i += 256) s += g_ds3[a * 256 * 169 + i];
    float ds3 = block_reduce(s) * (1.0f / (256.0f * 169.0f));

    float m3 = block_reduce(g_s1_3[a * 256 + t]) * (1.0f / 256.0f);
    float glb3 = expf(-2.0f * m3);

    s = 0.0f;
    for (int i = t; i < 512 * 25; i += 256) s += g_ds4[a * 512 * 25 + i];
    float ds4 = block_reduce(s) * (1.0f / (512.0f * 25.0f));

    s = 0.0f;
    for (int i = t; i < 512; i += 256) s += g_s1_4[a * 512 + i];
    float m4 = block_reduce(s) * (1.0f / 512.0f);
    float glb4 = expf(-2.0f * m4);

    if (t == 0) out[a] = ds3 * glb3 + ds4 * glb4;
}

extern "C" void kernel_launch(void* const* d_in, const int* in_sizes, int n_in,
                              void* d_out, int out_size) {
    const float* r3 = (const float*)d_in[0];
    const float* d3 = (const float*)d_in[1];
    const float* r4 = (const float*)d_in[2];
    const float* d4 = (const float*)d_in[3];
    float* out = (float*)d_out;

    mean_kernel<3, 64 * 64><<<4 * 256, 256>>>(r3, d3);
    mean_kernel<4, 32 * 32><<<4 * 512, 256>>>(r4, d4);

    // layer3: 4*256*169 = 173056 warps, 8 warps/block -> 21632 blocks (exact)
    patch_kernel<3, 256, 64, 64, 13, 13, 8><<<(4 * 256 * 169) / 8, 256>>>(r3, d3);
    // layer4: 4*512*25 = 51200 warps -> 6400 blocks (exact)
    patch_kernel<4, 512, 32, 32, 5, 5, 8><<<(4 * 512 * 25) / 8, 256>>>(r4, d4);

    final_kernel<<<4, 256>>>(out);
}

// round 3
// speedup vs baseline: 1.7809x; 1.7809x over previous
#include <cuda_runtime.h>
#include <math.h>

#define FULL 0xffffffffu

// Deterministic scratch (no device-side allocation allowed).
__device__ float g_ds3[4 * 256 * 169];
__device__ float g_ds4[4 * 512 * 25];
__device__ float g_s1_3[4 * 256];
__device__ float g_s1_4[4 * 512];

// Round-robin (circle method) schedule for 16 columns: 15 rounds x 8 disjoint pairs.
__host__ __device__ constexpr int rr_idx(int r, int k) {
    return (k == 0) ? 0 : ((k - 1 + r) % 15) + 1;
}

// ---------------------------------------------------------------------------
// Patch kernel: one warp per patch-pair.
//   lanes 0-15  : ref matrix P_r  (lane r holds row r, 16 registers)
//   lanes 16-31 : dist matrix P_d
// One-sided Jacobi with cached column norms + parallel (round-robin) ordering.
// ---------------------------------------------------------------------------
template <int LAYER, int C, int H, int W, int NH, int NW, int NSWEEP>
__global__ __launch_bounds__(128, 4) void patch_kernel(const float* __restrict__ ref,
                                                       const float* __restrict__ dist) {
    constexpr int NP = NH * NW;
    const int warpId = (blockIdx.x * blockDim.x + threadIdx.x) >> 5;
    const int lane = threadIdx.x & 31;
    const int sub = lane >> 4;   // 0 = ref, 1 = dist
    const int r = lane & 15;     // matrix row owned by this lane

    float* ds_out = (LAYER == 3) ? g_ds3 : g_ds4;

    int a = warpId / (C * NP);
    int rem = warpId - a * (C * NP);
    int b = rem / NP;
    int p = rem - b * NP;
    int ph = p / NW;
    int pw = p - ph * NW;

    const float* src = sub ? dist : ref;
    const float* base = src + (((size_t)(a * C + b)) * H + (size_t)(ph * 4)) * W + (pw * 4 + r);

    float v[16];
#pragma unroll
    for (int c = 0; c < 16; c++) v[c] = base[(size_t)c * W];

    // ---- initial column norms, replicated in every lane of each 16-half ----
    float n[16];
#pragma unroll
    for (int k = 0; k < 16; k++) n[k] = v[k] * v[k];
#pragma unroll
    for (int o = 1; o < 16; o <<= 1) {
#pragma unroll
        for (int k = 0; k < 16; k++) n[k] += __shfl_xor_sync(FULL, n[k], o);
    }

    // ---- one-sided Jacobi sweeps: 15 rounds of 8 independent pairs ----
#pragma unroll 1
    for (int sw = 0; sw < NSWEEP; sw++) {
#pragma unroll
        for (int rd = 0; rd < 15; rd++) {
            float prod[8];
#pragma unroll
            for (int m = 0; m < 8; m++) {
                const int pi = rr_idx(rd, m);
                const int qi = rr_idx(rd, 15 - m);
                prod[m] = v[pi] * v[qi];
            }
#pragma unroll
            for (int o = 1; o < 16; o <<= 1) {
#pragma unroll
                for (int m = 0; m < 8; m++)
                    prod[m] += __shfl_xor_sync(FULL, prod[m], o);
            }
#pragma unroll
            for (int m = 0; m < 8; m++) {
                const int pi = rr_idx(rd, m);
                const int qi = rr_idx(rd, 15 - m);
                float apq = prod[m];
                float D = n[qi] - n[pi];                 // aqq - app
                float h2 = fmaf(D, D, 4.0f * apq * apq);
                if (h2 > 1e-35f) {
                    float inv_h = rsqrtf(h2);
                    float c2 = fabsf(D) * inv_h;         // cos(2theta) >= 0
                    float sgn = copysignf(1.0f, D);
                    float s2 = 2.0f * apq * inv_h * sgn; // sin(2theta)
                    float u = fmaf(0.5f, c2, 0.5f);      // cos^2(theta)
                    float inv_su = rsqrtf(u);
                    float cc = u * inv_su;               // cos(theta)
                    float ss = 0.5f * s2 * inv_su;       // sin(theta)
                    float t = ss * inv_su;               // tan(theta) = s2/(2u)
                    float vp = v[pi], vq = v[qi];
                    v[pi] = fmaf(cc, vp, -ss * vq);
                    v[qi] = fmaf(ss, vp, cc * vq);
                    float tq = t * apq;
                    n[pi] = n[pi] - tq;
                    n[qi] = n[qi] + tq;
                }
            }
        }
    }

    // ---- exact column norms via transposing reduction: lane j gets ||col j||^2 ----
    float acc[16];
#pragma unroll
    for (int j = 0; j < 16; j++) acc[j] = v[j] * v[j];

    float a8[8];
#pragma unroll
    for (int m = 0; m < 8; m++) {
        bool hi = (r & 1);
        float send = hi ? acc[2 * m] : acc[2 * m + 1];
        float recv = __shfl_xor_sync(FULL, send, 1);
        a8[m] = (hi ? acc[2 * m + 1] : acc[2 * m]) + recv;
    }
    float a4v[4];
#pragma unroll
    for (int m = 0; m < 4; m++) {
        bool hi = (r & 2);
        float send = hi ? a8[2 * m] : a8[2 * m + 1];
        float recv = __shfl_xor_sync(FULL, send, 2);
        a4v[m] = (hi ? a8[2 * m + 1] : a8[2 * m]) + recv;
    }
    float a2v[2];
#pragma unroll
    for (int m = 0; m < 2; m++) {
        bool hi = (r & 4);
        float send = hi ? a4v[2 * m] : a4v[2 * m + 1];
        float recv = __shfl_xor_sync(FULL, send, 4);
        a2v[m] = (hi ? a4v[2 * m + 1] : a4v[2 * m]) + recv;
    }
    float a1;
    {
        bool hi = (r & 8);
        float send = hi ? a2v[0] : a2v[1];
        float recv = __shfl_xor_sync(FULL, send, 8);
        a1 = (hi ? a2v[1] : a2v[0]) + recv;
    }
    float s_local = sqrtf(a1);   // sigma of column r (held by lane r)

    // ---- broadcast sigmas, compute descending ranks (ties broken by index) ----
    const int base_lane = lane & 16;
    float s_all[16];
#pragma unroll
    for (int k = 0; k < 16; k++) s_all[k] = __shfl_sync(FULL, s_local, base_lane + k);
    int rk = 0;
#pragma unroll
    for (int k = 0; k < 16; k++)
        rk += (int)((s_all[k] > s_local) || (s_all[k] == s_local && k < r));
    int rank_all[16];
#pragma unroll
    for (int k = 0; k < 16; k++) rank_all[k] = __shfl_sync(FULL, rk, base_lane + k);

    // ---- stage sorted, normalized U and sorted sigmas in shared memory ----
    __shared__ float Ush[4][2][16][16];   // [warp][sub][sorted_col][row]
    __shared__ float Ssh[4][2][16];       // [warp][sub][sorted_col]
    const int wl = threadIdx.x >> 5;
    Ssh[wl][sub][rk] = s_local;
#pragma unroll
    for (int j = 0; j < 16; j++) {
        Ush[wl][sub][rank_all[j]][r] = v[j] * __fdividef(1.0f, s_all[j] + 1e-30f);
    }
    __syncwarp();

    // ---- combine ref/dist: u_rd per row, diff of sorted sigmas ----
    float urd = 0.0f;
#pragma unroll
    for (int i = 0; i < 16; i++)
        urd += fabsf(Ush[wl][0][i][r] * Ush[wl][1][i][r]);
    float d = Ssh[wl][0][r] - Ssh[wl][1][r];

    float sd = d * d;
    float su = urd;
    float sq2 = urd * urd;
#pragma unroll
    for (int o = 1; o < 16; o <<= 1) {
        sd += __shfl_xor_sync(FULL, sd, o);
        su += __shfl_xor_sync(FULL, su, o);
        sq2 += __shfl_xor_sync(FULL, sq2, o);
    }
    if (lane == 0) {
        float mean = su * (1.0f / 16.0f);
        float var = (sq2 - su * su * (1.0f / 16.0f)) * (1.0f / 15.0f);  // ddof=1
        float wt = sqrtf(fmaxf(var, 0.0f)) * __fdividef(1.0f, mean + 1e-9f);
        ds_out[warpId] = sd * wt;
    }
}

// ---------------------------------------------------------------------------
// Per-channel global means -> s1 term.
// ---------------------------------------------------------------------------
template <int LAYER, int HW>
__global__ __launch_bounds__(256) void mean_kernel(const float* __restrict__ ref,
                                                   const float* __restrict__ dist) {
    float* s1out = (LAYER == 3) ? g_s1_3 : g_s1_4;
    const int ac = blockIdx.x;
    const float* rp = ref + (size_t)ac * HW;
    const float* dp = dist + (size_t)ac * HW;
    float sr = 0.0f, sdd = 0.0f;
    for (int i = threadIdx.x; i < HW; i += 256) {
        sr += rp[i];
        sdd += dp[i];
    }
    __shared__ float shr[256], shd[256];
    shr[threadIdx.x] = sr;
    shd[threadIdx.x] = sdd;
    __syncthreads();
    for (int o = 128; o > 0; o >>= 1) {
        if (threadIdx.x < o) {
            shr[threadIdx.x] += shr[threadIdx.x + o];
            shd[threadIdx.x] += shd[threadIdx.x + o];
        }
        __syncthreads();
    }
    if (threadIdx.x == 0) {
        float ym = shr[0] * (1.0f / HW);   // ref mean
        float xm = shd[0] * (1.0f / HW);   // dist mean
        float s1 = (2.0f * xm * ym + 1e-6f) / (xm * xm + ym * ym + 1e-6f);
        s1out[ac] = s1;
    }
}

// ---------------------------------------------------------------------------
// Final deterministic reduction: block a computes out[a].
// ---------------------------------------------------------------------------
__global__ __launch_bounds__(256) void final_kernel(float* __restrict__ out) {
    const int a = blockIdx.x;
    const int t = threadIdx.x;
    __shared__ float sh[256];

    auto block_reduce = [&](float vloc) -> float {
        sh[t] = vloc;
        __syncthreads();
        for (int o = 128; o > 0; o >>= 1) {
            if (t < o) sh[t] += sh[t + o];
            __syncthreads();
        }
        float res = sh[0];
        __syncthreads();
        return res;
    };

    float s = 0.0f;
    for (int i = t; i < 256 * 169; i += 256) s += g_ds3[a * 256 * 169 + i];
    float ds3 = block_reduce(s) * (1.0f / (256.0f * 169.0f));

    float m3 = block_reduce(g_s1_3[a * 256 + t]) * (1.0f / 256.0f);
    float glb3 = expf(-2.0f * m3);

    s = 0.0f;
    for (int i = t; i < 512 * 25; i += 256) s += g_ds4[a * 512 * 25 + i];
    float ds4 = block_reduce(s) * (1.0f / (512.0f * 25.0f));

    s = 0.0f;
    for (int i = t; i < 512; i += 256) s += g_s1_4[a * 512 + i];
    float m4 = block_reduce(s) * (1.0f / 512.0f);
    float glb4 = expf(-2.0f * m4);

    if (t == 0) out[a] = ds3 * glb3 + ds4 * glb4;
}

extern "C" void kernel_launch(void* const* d_in, const int* in_sizes, int n_in,
                              void* d_out, int out_size) {
    const float* r3 = (const float*)d_in[0];
    const float* d3 = (const float*)d_in[1];
    const float* r4 = (const float*)d_in[2];
    const float* d4 = (const float*)d_in[3];
    float* out = (float*)d_out;

    mean_kernel<3, 64 * 64><<<4 * 256, 256>>>(r3, d3);
    mean_kernel<4, 32 * 32><<<4 * 512, 256>>>(r4, d4);

    // layer3: 4*256*169 = 173056 warps, 4 warps/block -> 43264 blocks (exact)
    patch_kernel<3, 256, 64, 64, 13, 13, 6><<<(4 * 256 * 169) / 4, 128>>>(r3, d3);
    // layer4: 4*512*25 = 51200 warps -> 12800 blocks (exact)
    patch_kernel<4, 512, 32, 32, 5, 5, 6><<<(4 * 512 * 25) / 4, 128>>>(r4, d4);

    final_kernel<<<4, 256>>>(out);
}

// round 5
// speedup vs baseline: 6.5684x; 3.6883x over previous
#include <cuda_runtime.h>
#include <math.h>

#define FULL 0xffffffffu

// Deterministic scratch (no device-side allocation allowed).
__device__ float g_ds3[4 * 256 * 169];
__device__ float g_ds4[4 * 512 * 25];
__device__ float g_s1_3[4 * 256];
__device__ float g_s1_4[4 * 512];

// Round-robin (circle method) schedule for 16 columns: 15 rounds x 8 disjoint pairs.
__host__ __device__ constexpr int rr_idx(int r, int k) {
    return (k == 0) ? 0 : ((k - 1 + r) % 15) + 1;
}

// ---------------------------------------------------------------------------
// Patch kernel: one warp per patch-pair.
//   lanes 0-15  : ref matrix P_r  (lane r holds row r, 16 registers)
//   lanes 16-31 : dist matrix P_d
// One-sided Jacobi. Per round: 8 disjoint pairs; Gram products are
// transpose-reduced so lane m holds apq_m; rotation math computed ONCE in
// lane m (not redundantly in all lanes) and (cc,ss) broadcast back.
// Column norms live transposed: lane r holds d = ||col r||^2, updated
// incrementally (n_p -= t*apq, n_q += t*apq) via one shuffled tq per round.
// ---------------------------------------------------------------------------
template <int LAYER, int C, int H, int W, int NH, int NW, int NSWEEP>
__global__ __launch_bounds__(128, 4) void patch_kernel(const float* __restrict__ ref,
                                                       const float* __restrict__ dist) {
    constexpr int NP = NH * NW;
    const int warpId = (blockIdx.x * blockDim.x + threadIdx.x) >> 5;
    const int lane = threadIdx.x & 31;
    const int sub = lane >> 4;   // 0 = ref, 1 = dist
    const int r = lane & 15;     // matrix row owned by this lane
    const int half = lane & 16;  // shuffle-source base for this half

    float* ds_out = (LAYER == 3) ? g_ds3 : g_ds4;

    int a = warpId / (C * NP);
    int rem = warpId - a * (C * NP);
    int b = rem / NP;
    int p = rem - b * NP;
    int ph = p / NW;
    int pw = p - ph * NW;

    const float* src = sub ? dist : ref;
    const float* base = src + (((size_t)(a * C + b)) * H + (size_t)(ph * 4)) * W + (pw * 4 + r);

    float v[16];
#pragma unroll
    for (int c = 0; c < 16; c++) v[c] = base[(size_t)c * W];

    // ---- initial column norms, transposed: lane r gets d = ||col r||^2 ----
    float d;
    {
        float acc[16];
#pragma unroll
        for (int j = 0; j < 16; j++) acc[j] = v[j] * v[j];
        float a8[8];
#pragma unroll
        for (int m = 0; m < 8; m++) {
            bool hi = (r & 1);
            float send = hi ? acc[2 * m] : acc[2 * m + 1];
            float recv = __shfl_xor_sync(FULL, send, 1);
            a8[m] = (hi ? acc[2 * m + 1] : acc[2 * m]) + recv;
        }
        float a4v[4];
#pragma unroll
        for (int m = 0; m < 4; m++) {
            bool hi = (r & 2);
            float send = hi ? a8[2 * m] : a8[2 * m + 1];
            float recv = __shfl_xor_sync(FULL, send, 2);
            a4v[m] = (hi ? a8[2 * m + 1] : a8[2 * m]) + recv;
        }
        float a2v[2];
#pragma unroll
        for (int m = 0; m < 2; m++) {
            bool hi = (r & 4);
            float send = hi ? a4v[2 * m] : a4v[2 * m + 1];
            float recv = __shfl_xor_sync(FULL, send, 4);
            a2v[m] = (hi ? a4v[2 * m + 1] : a4v[2 * m]) + recv;
        }
        bool hi = (r & 8);
        float send = hi ? a2v[0] : a2v[1];
        float recv = __shfl_xor_sync(FULL, send, 8);
        d = (hi ? a2v[1] : a2v[0]) + recv;
    }

    const int mm = lane & 7;   // pair index this lane's angle computation owns

    // ---- Jacobi sweeps ----
#pragma unroll 1
    for (int sw = 0; sw < NSWEEP; sw++) {
#pragma unroll
        for (int rd = 0; rd < 15; rd++) {
            // Gram products for the 8 disjoint pairs (static indices).
            float prod[8];
#pragma unroll
            for (int m = 0; m < 8; m++)
                prod[m] = v[rr_idx(rd, m)] * v[rr_idx(rd, 15 - m)];

            // Transpose-reduce: lane (&7)==m ends with apq_m (16-lane sum).
            float b4[4];
#pragma unroll
            for (int t = 0; t < 4; t++) {
                bool hi = (lane & 1);
                float send = hi ? prod[2 * t] : prod[2 * t + 1];
                float recv = __shfl_xor_sync(FULL, send, 1);
                b4[t] = (hi ? prod[2 * t + 1] : prod[2 * t]) + recv;
            }
            float b2[2];
#pragma unroll
            for (int t = 0; t < 2; t++) {
                bool hi = (lane & 2);
                float send = hi ? b4[2 * t] : b4[2 * t + 1];
                float recv = __shfl_xor_sync(FULL, send, 2);
                b2[t] = (hi ? b4[2 * t + 1] : b4[2 * t]) + recv;
            }
            float b1;
            {
                bool hi = (lane & 4);
                float send = hi ? b2[0] : b2[1];
                float recv = __shfl_xor_sync(FULL, send, 4);
                b1 = (hi ? b2[1] : b2[0]) + recv;
            }
            float apq = b1 + __shfl_xor_sync(FULL, b1, 8);

            // This lane's pair column indices (runtime ints; only shuffle src).
            int xp = mm - 1 + rd;
            xp = (xp >= 15) ? xp - 15 : xp;
            int pm = (mm == 0) ? 0 : (xp + 1);
            int yq = 14 - mm + rd;
            yq = (yq >= 15) ? yq - 15 : yq;
            int qm = yq + 1;

            float dp = __shfl_sync(FULL, d, half | pm);
            float dq = __shfl_sync(FULL, d, half | qm);

            // Rotation angle (computed once per pair, here).
            float D = dq - dp;
            float apq2 = apq * apq;
            float h2 = fmaf(D, D, 4.0f * apq2);
            bool ok = (h2 > 1e-30f);
            float inv_h = rsqrtf(fmaxf(h2, 1e-37f));
            float c2 = fabsf(D) * inv_h;              // cos(2theta) >= 0
            float s2 = 2.0f * apq * inv_h * copysignf(1.0f, D);
            float u = fmaf(0.5f, c2, 0.5f);           // cos^2(theta) in [0.5,1]
            float inv_su = rsqrtf(u);
            float cc = u * inv_su;                    // cos(theta)
            float ss = 0.5f * s2 * inv_su;            // sin(theta)
            float t = ss * inv_su;                    // tan(theta)
            float tq = t * apq;
            cc = ok ? cc : 1.0f;
            ss = ok ? ss : 0.0f;
            tq = ok ? tq : 0.0f;

            // Broadcast rotation coefficients from lane m of each half.
            float ccv[8], ssv[8];
#pragma unroll
            for (int m = 0; m < 8; m++) {
                ccv[m] = __shfl_sync(FULL, cc, half | m);
                ssv[m] = __shfl_sync(FULL, ss, half | m);
            }

            // Own-column norm update: column r is in exactly one pair.
            {
                int z = r - 1 - rd;
                z = (z < 0) ? z + 15 : z;
                int k = (r == 0) ? 0 : (z + 1);       // position of col r in round rd
                int mk = (k <= 7) ? k : 15 - k;       // its pair index
                float tqk = __shfl_sync(FULL, tq, half | mk);
                d += (k <= 7) ? -tqk : tqk;           // p side: -tq, q side: +tq
            }

            // Apply the 8 rotations to this lane's row (static indices).
#pragma unroll
            for (int m = 0; m < 8; m++) {
                const int pi = rr_idx(rd, m);
                const int qi = rr_idx(rd, 15 - m);
                float vp = v[pi], vq = v[qi];
                v[pi] = fmaf(ccv[m], vp, -ssv[m] * vq);
                v[qi] = fmaf(ssv[m], vp, ccv[m] * vq);
            }
        }
    }

    float s_local = sqrtf(fmaxf(d, 0.0f));   // sigma of column r (held by lane r)

    // ---- broadcast sigmas, compute descending ranks (ties broken by index) ----
    float s_all[16];
#pragma unroll
    for (int k = 0; k < 16; k++) s_all[k] = __shfl_sync(FULL, s_local, half + k);
    int rk = 0;
#pragma unroll
    for (int k = 0; k < 16; k++)
        rk += (int)((s_all[k] > s_local) || (s_all[k] == s_local && k < r));
    int rank_all[16];
#pragma unroll
    for (int k = 0; k < 16; k++) rank_all[k] = __shfl_sync(FULL, rk, half + k);

    // ---- stage sorted, normalized U and sorted sigmas in shared memory ----
    __shared__ float Ush[4][2][16][16];   // [warp][sub][sorted_col][row]
    __shared__ float Ssh[4][2][16];       // [warp][sub][sorted_col]
    const int wl = threadIdx.x >> 5;
    Ssh[wl][sub][rk] = s_local;
#pragma unroll
    for (int j = 0; j < 16; j++) {
        Ush[wl][sub][rank_all[j]][r] = v[j] * __fdividef(1.0f, s_all[j] + 1e-30f);
    }
    __syncwarp();

    // ---- combine ref/dist: u_rd per row, diff of sorted sigmas ----
    float urd = 0.0f;
#pragma unroll
    for (int i = 0; i < 16; i++)
        urd += fabsf(Ush[wl][0][i][r] * Ush[wl][1][i][r]);
    float dd = Ssh[wl][0][r] - Ssh[wl][1][r];

    float sd = dd * dd;
    float su = urd;
    float sq2 = urd * urd;
#pragma unroll
    for (int o = 1; o < 16; o <<= 1) {
        sd += __shfl_xor_sync(FULL, sd, o);
        su += __shfl_xor_sync(FULL, su, o);
        sq2 += __shfl_xor_sync(FULL, sq2, o);
    }
    if (lane == 0) {
        float mean = su * (1.0f / 16.0f);
        float var = (sq2 - su * su * (1.0f / 16.0f)) * (1.0f / 15.0f);  // ddof=1
        float wt = sqrtf(fmaxf(var, 0.0f)) * __fdividef(1.0f, mean + 1e-9f);
        ds_out[warpId] = sd * wt;
    }
}

// ---------------------------------------------------------------------------
// Per-channel global means -> s1 term.
// ---------------------------------------------------------------------------
template <int LAYER, int HW>
__global__ __launch_bounds__(256) void mean_kernel(const float* __restrict__ ref,
                                                   const float* __restrict__ dist) {
    float* s1out = (LAYER == 3) ? g_s1_3 : g_s1_4;
    const int ac = blockIdx.x;
    const float* rp = ref + (size_t)ac * HW;
    const float* dp = dist + (size_t)ac * HW;
    float sr = 0.0f, sdd = 0.0f;
    for (int i = threadIdx.x; i < HW; i += 256) {
        sr += rp[i];
        sdd += dp[i];
    }
    __shared__ float shr[256], shd[256];
    shr[threadIdx.x] = sr;
    shd[threadIdx.x] = sdd;
    __syncthreads();
    for (int o = 128; o > 0; o >>= 1) {
        if (threadIdx.x < o) {
            shr[threadIdx.x] += shr[threadIdx.x + o];
            shd[threadIdx.x] += shd[threadIdx.x + o];
        }
        __syncthreads();
    }
    if (threadIdx.x == 0) {
        float ym = shr[0] * (1.0f / HW);   // ref mean
        float xm = shd[0] * (1.0f / HW);   // dist mean
        float s1 = (2.0f * xm * ym + 1e-6f) / (xm * xm + ym * ym + 1e-6f);
        s1out[ac] = s1;
    }
}

// ---------------------------------------------------------------------------
// Final deterministic reduction: block a computes out[a].
// ---------------------------------------------------------------------------
__global__ __launch_bounds__(256) void final_kernel(float* __restrict__ out) {
    const int a = blockIdx.x;
    const int t = threadIdx.x;
    __shared__ float sh[256];

    auto block_reduce = [&](float vloc) -> float {
        sh[t] = vloc;
        __syncthreads();
        for (int o = 128; o > 0; o >>= 1) {
            if (t < o) sh[t] += sh[t + o];
            __syncthreads();
        }
        float res = sh[0];
        __syncthreads();
        return res;
    };

    float s = 0.0f;
    for (int i = t; i < 256 * 169; i += 256) s += g_ds3[a * 256 * 169 + i];
    float ds3 = block_reduce(s) * (1.0f / (256.0f * 169.0f));

    float m3 = block_reduce(g_s1_3[a * 256 + t]) * (1.0f / 256.0f);
    float glb3 = expf(-2.0f * m3);

    s = 0.0f;
    for (int i = t; i < 512 * 25; i += 256) s += g_ds4[a * 512 * 25 + i];
    float ds4 = block_reduce(s) * (1.0f / (512.0f * 25.0f));

    s = 0.0f;
    for (int i = t; i < 512; i += 256) s += g_s1_4[a * 512 + i];
    float m4 = block_reduce(s) * (1.0f / 512.0f);
    float glb4 = expf(-2.0f * m4);

    if (t == 0) out[a] = ds3 * glb3 + ds4 * glb4;
}

extern "C" void kernel_launch(void* const* d_in, const int* in_sizes, int n_in,
                              void* d_out, int out_size) {
    const float* r3 = (const float*)d_in[0];
    const float* d3 = (const float*)d_in[1];
    const float* r4 = (const float*)d_in[2];
    const float* d4 = (const float*)d_in[3];
    float* out = (float*)d_out;

    mean_kernel<3, 64 * 64><<<4 * 256, 256>>>(r3, d3);
    mean_kernel<4, 32 * 32><<<4 * 512, 256>>>(r4, d4);

    // layer3: 4*256*169 = 173056 warps, 4 warps/block -> 43264 blocks (exact)
    patch_kernel<3, 256, 64, 64, 13, 13, 5><<<(4 * 256 * 169) / 4, 128>>>(r3, d3);
    // layer4: 4*512*25 = 51200 warps -> 12800 blocks (exact)
    patch_kernel<4, 512, 32, 32, 5, 5, 5><<<(4 * 512 * 25) / 4, 128>>>(r4, d4);

    final_kernel<<<4, 256>>>(out);
}

// round 6
// speedup vs baseline: 9.1399x; 1.3915x over previous
#include <cuda_runtime.h>
#include <math.h>

#define FULL 0xffffffffu

// Deterministic scratch (no device-side allocation allowed).
__device__ float g_ds3[4 * 256 * 169];
__device__ float g_ds4[4 * 512 * 25];
__device__ float g_s1_3[4 * 256];
__device__ float g_s1_4[4 * 512];

// Round-robin (circle method) schedule: 15 rounds x 8 disjoint position-pairs.
// Position k holds column rr_idx(rd, k); position 0 is pinned to column 0.
__host__ __device__ constexpr int rr_idx(int r, int k) {
    return (k == 0) ? 0 : ((k - 1 + r) % 15) + 1;
}

// ---------------------------------------------------------------------------
// Patch kernel: one warp = TWO patch-pairs (4 matrices of 16x16).
//   group g = lane>>3 : matrix index. g0,g1 = pair A (ref,dist); g2,g3 = pair B.
//   Within a group, lane m = lane&7 owns rows m and m+8 (vA[16], vB[16]).
// One-sided Jacobi, static schedule:
//   - Gram products of the 8 position-pairs: 2-row FMA per lane, then a
//     3-level transposing butterfly over the 8 group lanes -> lane m holds apq_m.
//   - Lane m also holds dp,dq = squared norms of the columns at positions
//     (m, 15-m) == its own pair, so the rotation angle is computed locally.
//   - cc,ss broadcast with static sources; rotations applied to both rows.
//   - Between rounds the circle permutation moves norms: 2 static shuffles.
// ---------------------------------------------------------------------------
template <int LAYER, int C, int H, int W, int NH, int NW, int NSWEEP>
__global__ __launch_bounds__(128, 5) void patch_kernel(const float* __restrict__ ref,
                                                       const float* __restrict__ dist) {
    constexpr int NP = NH * NW;
    const int warpId = (blockIdx.x * blockDim.x + threadIdx.x) >> 5;
    const int lane = threadIdx.x & 31;
    const int g = lane >> 3;       // matrix group 0..3
    const int m = lane & 7;        // pair index / lane-in-group
    const int gb = lane & 24;      // group base lane
    const int sub = g & 1;         // 0 = ref, 1 = dist
    const int prl = g >> 1;        // which patch-pair this group serves

    float* ds_out = (LAYER == 3) ? g_ds3 : g_ds4;

    const int pairIdx = warpId * 2 + prl;
    int a = pairIdx / (C * NP);
    int rem = pairIdx - a * (C * NP);
    int b = rem / NP;
    int p = rem - b * NP;
    int ph = p / NW;
    int pw = p - ph * NW;

    const float* src = sub ? dist : ref;
    const float* base = src + (((size_t)(a * C + b)) * H + (size_t)(ph * 4)) * W + (pw * 4);

    // vA = row m, vB = row m+8; column c of the (swapaxed) patch = base[c*W + row]
    float vA[16], vB[16];
#pragma unroll
    for (int c = 0; c < 16; c++) {
        vA[c] = base[(size_t)c * W + m];
        vB[c] = base[(size_t)c * W + m + 8];
    }

    // ---- initial column norms: 3-level transposing reduce over the 8 lanes.
    // After: lane m holds n0=||col m||^2 (a2[0]) and n1=||col m+8||^2 (a2[1]).
    float dp, dq;
    {
        float acc[16];
#pragma unroll
        for (int j = 0; j < 16; j++) acc[j] = fmaf(vB[j], vB[j], vA[j] * vA[j]);
        float a8[8];
#pragma unroll
        for (int t = 0; t < 8; t++) {
            bool hi = (lane & 1);
            float send = hi ? acc[2 * t] : acc[2 * t + 1];
            float recv = __shfl_xor_sync(FULL, send, 1);
            a8[t] = (hi ? acc[2 * t + 1] : acc[2 * t]) + recv;
        }
        float a4[4];
#pragma unroll
        for (int t = 0; t < 4; t++) {
            bool hi = (lane & 2);
            float send = hi ? a8[2 * t] : a8[2 * t + 1];
            float recv = __shfl_xor_sync(FULL, send, 2);
            a4[t] = (hi ? a8[2 * t + 1] : a8[2 * t]) + recv;
        }
        float a2[2];
#pragma unroll
        for (int t = 0; t < 2; t++) {
            bool hi = (lane & 4);
            float send = hi ? a4[2 * t] : a4[2 * t + 1];
            float recv = __shfl_xor_sync(FULL, send, 4);
            a2[t] = (hi ? a4[2 * t + 1] : a4[2 * t]) + recv;
        }
        dp = a2[0];                                    // pos m     = col m  (rd=0)
        dq = __shfl_xor_sync(FULL, a2[1], 7);          // pos 15-m  = col (7-m)+8 = 15-m
    }

    // ---- Jacobi sweeps ----
#pragma unroll 1
    for (int sw = 0; sw < NSWEEP; sw++) {
#pragma unroll
        for (int rd = 0; rd < 15; rd++) {
            // Gram products of the 8 position-pairs (2 rows each, static idx).
            float prod[8];
#pragma unroll
            for (int k = 0; k < 8; k++) {
                const int pi = rr_idx(rd, k);
                const int qi = rr_idx(rd, 15 - k);
                prod[k] = fmaf(vB[pi], vB[qi], vA[pi] * vA[qi]);
            }
            // 3-level transposing reduce: lane m ends with apq_m (16-row sum).
            float c4[4];
#pragma unroll
            for (int t = 0; t < 4; t++) {
                bool hi = (lane & 1);
                float send = hi ? prod[2 * t] : prod[2 * t + 1];
                float recv = __shfl_xor_sync(FULL, send, 1);
                c4[t] = (hi ? prod[2 * t + 1] : prod[2 * t]) + recv;
            }
            float c2[2];
#pragma unroll
            for (int t = 0; t < 2; t++) {
                bool hi = (lane & 2);
                float send = hi ? c4[2 * t] : c4[2 * t + 1];
                float recv = __shfl_xor_sync(FULL, send, 2);
                c2[t] = (hi ? c4[2 * t + 1] : c4[2 * t]) + recv;
            }
            float apq;
            {
                bool hi = (lane & 4);
                float send = hi ? c2[0] : c2[1];
                float recv = __shfl_xor_sync(FULL, send, 4);
                apq = (hi ? c2[1] : c2[0]) + recv;
            }

            // Rotation angle — all inputs local to this lane.
            float D = dq - dp;
            float h2 = fmaf(D, D, 4.0f * apq * apq);
            bool ok = (h2 > 1e-30f);
            float inv_h = rsqrtf(fmaxf(h2, 1e-37f));
            float c2a = fabsf(D) * inv_h;               // cos(2theta) >= 0
            float s2a = 2.0f * apq * inv_h * copysignf(1.0f, D);
            float u = fmaf(0.5f, c2a, 0.5f);            // cos^2(theta)
            float inv_su = rsqrtf(u);
            float cc = u * inv_su;                      // cos(theta)
            float ss = 0.5f * s2a * inv_su;             // sin(theta)
            float tq = ss * inv_su * apq;               // tan(theta)*apq
            cc = ok ? cc : 1.0f;
            ss = ok ? ss : 0.0f;
            tq = ok ? tq : 0.0f;

            // Broadcast rotation coefficients within each 8-lane group (static src).
            float ccv[8], ssv[8];
#pragma unroll
            for (int k = 0; k < 8; k++) {
                ccv[k] = __shfl_sync(FULL, cc, gb | k);
                ssv[k] = __shfl_sync(FULL, ss, gb | k);
            }

            // Apply the 8 rotations to both owned rows (static indices).
#pragma unroll
            for (int k = 0; k < 8; k++) {
                const int pi = rr_idx(rd, k);
                const int qi = rr_idx(rd, 15 - k);
                float ap = vA[pi], aq = vA[qi];
                vA[pi] = fmaf(ccv[k], ap, -ssv[k] * aq);
                vA[qi] = fmaf(ssv[k], ap, ccv[k] * aq);
                float bp = vB[pi], bq = vB[qi];
                vB[pi] = fmaf(ccv[k], bp, -ssv[k] * bq);
                vB[qi] = fmaf(ssv[k], bp, ccv[k] * bq);
            }

            // Local norm update, then circle-permute norms for the next round:
            // new dp_m = old dp_{m+1} (m=1..6), m=7: own old dq, m=0: unchanged.
            // new dq_m = old dq_{m-1} (m>=1), m=0: old dp_1.
            dp -= tq;
            dq += tq;
            float t1 = __shfl_sync(FULL, dp, gb | ((m + 1) & 7));
            float t2 = __shfl_sync(FULL, dq, gb | ((m - 1) & 7));
            float ndp = (m == 0) ? dp : ((m == 7) ? dq : t1);
            float ndq = (m == 0) ? t1 : t2;
            dp = ndp;
            dq = ndq;
        }
    }
    // NSWEEP*15 rounds => permutation is identity again (15 | rounds).

    // ---- exact final column norms (fixes incremental drift): lane m -> cols m, m+8
    float n0, n1;
    {
        float acc[16];
#pragma unroll
        for (int j = 0; j < 16; j++) acc[j] = fmaf(vB[j], vB[j], vA[j] * vA[j]);
        float a8[8];
#pragma unroll
        for (int t = 0; t < 8; t++) {
            bool hi = (lane & 1);
            float send = hi ? acc[2 * t] : acc[2 * t + 1];
            float recv = __shfl_xor_sync(FULL, send, 1);
            a8[t] = (hi ? acc[2 * t + 1] : acc[2 * t]) + recv;
        }
        float a4[4];
#pragma unroll
        for (int t = 0; t < 4; t++) {
            bool hi = (lane & 2);
            float send = hi ? a8[2 * t] : a8[2 * t + 1];
            float recv = __shfl_xor_sync(FULL, send, 2);
            a4[t] = (hi ? a8[2 * t + 1] : a8[2 * t]) + recv;
        }
        float a2[2];
#pragma unroll
        for (int t = 0; t < 2; t++) {
            bool hi = (lane & 4);
            float send = hi ? a4[2 * t] : a4[2 * t + 1];
            float recv = __shfl_xor_sync(FULL, send, 4);
            a2[t] = (hi ? a4[2 * t + 1] : a4[2 * t]) + recv;
        }
        n0 = a2[0];
        n1 = a2[1];
    }
    float s0 = sqrtf(fmaxf(n0, 0.0f));   // sigma of col m
    float s1 = sqrtf(fmaxf(n1, 0.0f));   // sigma of col m+8

    // ---- epilogue via shared memory (per warp: 4 matrices) ----
    __shared__ float sig[4][4][16];
    __shared__ float sigS[4][4][16];
    __shared__ float invs[4][4][16];
    __shared__ int rnk[4][4][16];
    __shared__ float Ush[4][4][16][16];   // [warp][group][sorted_col][row]
    const int wl = threadIdx.x >> 5;

    sig[wl][g][m] = s0;
    sig[wl][g][m + 8] = s1;
    invs[wl][g][m] = __fdividef(1.0f, s0 + 1e-30f);
    invs[wl][g][m + 8] = __fdividef(1.0f, s1 + 1e-30f);
    __syncwarp();

    // descending ranks, ties broken by column index
    {
        float sv[16];
#pragma unroll
        for (int k = 0; k < 16; k++) sv[k] = sig[wl][g][k];
        int rk0 = 0, rk1 = 0;
#pragma unroll
        for (int k = 0; k < 16; k++) {
            rk0 += (int)((sv[k] > s0) || (sv[k] == s0 && k < m));
            rk1 += (int)((sv[k] > s1) || (sv[k] == s1 && k < m + 8));
        }
        rnk[wl][g][m] = rk0;
        rnk[wl][g][m + 8] = rk1;
        sigS[wl][g][rk0] = s0;
        sigS[wl][g][rk1] = s1;
    }
    __syncwarp();

    // stage sorted, normalized U (this lane owns rows m and m+8)
#pragma unroll
    for (int j = 0; j < 16; j++) {
        int rj = rnk[wl][g][j];
        float iv = invs[wl][g][j];
        Ush[wl][g][rj][m] = vA[j] * iv;
        Ush[wl][g][rj][m + 8] = vB[j] * iv;
    }
    __syncwarp();

    // combine ref/dist per pair: lanes 0-15 -> pair 0, lanes 16-31 -> pair 1
    const int pr = lane >> 4;
    const int row = lane & 15;
    float urd = 0.0f;
#pragma unroll
    for (int i = 0; i < 16; i++)
        urd += fabsf(Ush[wl][2 * pr][i][row] * Ush[wl][2 * pr + 1][i][row]);
    float dd = sigS[wl][2 * pr][row] - sigS[wl][2 * pr + 1][row];

    float sd = dd * dd;
    float su = urd;
    float sq2 = urd * urd;
#pragma unroll
    for (int o = 1; o < 16; o <<= 1) {
        sd += __shfl_xor_sync(FULL, sd, o);
        su += __shfl_xor_sync(FULL, su, o);
        sq2 += __shfl_xor_sync(FULL, sq2, o);
    }
    if (row == 0) {
        float mean = su * (1.0f / 16.0f);
        float var = (sq2 - su * su * (1.0f / 16.0f)) * (1.0f / 15.0f);  // ddof=1
        float wt = sqrtf(fmaxf(var, 0.0f)) * __fdividef(1.0f, mean + 1e-9f);
        ds_out[warpId * 2 + pr] = sd * wt;
    }
}

// ---------------------------------------------------------------------------
// Per-channel global means -> s1 term.
// ---------------------------------------------------------------------------
template <int LAYER, int HW>
__global__ __launch_bounds__(256) void mean_kernel(const float* __restrict__ ref,
                                                   const float* __restrict__ dist) {
    float* s1out = (LAYER == 3) ? g_s1_3 : g_s1_4;
    const int ac = blockIdx.x;
    const float* rp = ref + (size_t)ac * HW;
    const float* dp = dist + (size_t)ac * HW;
    float sr = 0.0f, sdd = 0.0f;
    for (int i = threadIdx.x; i < HW; i += 256) {
        sr += rp[i];
        sdd += dp[i];
    }
    __shared__ float shr[256], shd[256];
    shr[threadIdx.x] = sr;
    shd[threadIdx.x] = sdd;
    __syncthreads();
    for (int o = 128; o > 0; o >>= 1) {
        if (threadIdx.x < o) {
            shr[threadIdx.x] += shr[threadIdx.x + o];
            shd[threadIdx.x] += shd[threadIdx.x + o];
        }
        __syncthreads();
    }
    if (threadIdx.x == 0) {
        float ym = shr[0] * (1.0f / HW);   // ref mean
        float xm = shd[0] * (1.0f / HW);   // dist mean
        float s1 = (2.0f * xm * ym + 1e-6f) / (xm * xm + ym * ym + 1e-6f);
        s1out[ac] = s1;
    }
}

// ---------------------------------------------------------------------------
// Final deterministic reduction: block a computes out[a].
// ---------------------------------------------------------------------------
__global__ __launch_bounds__(256) void final_kernel(float* __restrict__ out) {
    const int a = blockIdx.x;
    const int t = threadIdx.x;
    __shared__ float sh[256];

    auto block_reduce = [&](float vloc) -> float {
        sh[t] = vloc;
        __syncthreads();
        for (int o = 128; o > 0; o >>= 1) {
            if (t < o) sh[t] += sh[t + o];
            __syncthreads();
        }
        float res = sh[0];
        __syncthreads();
        return res;
    };

    float s = 0.0f;
    for (int i = t; i < 256 * 169; i += 256) s += g_ds3[a * 256 * 169 + i];
    float ds3 = block_reduce(s) * (1.0f / (256.0f * 169.0f));

    float m3 = block_reduce(g_s1_3[a * 256 + t]) * (1.0f / 256.0f);
    float glb3 = expf(-2.0f * m3);

    s = 0.0f;
    for (int i = t; i < 512 * 25; i += 256) s += g_ds4[a * 512 * 25 + i];
    float ds4 = block_reduce(s) * (1.0f / (512.0f * 25.0f));

    s = 0.0f;
    for (int i = t; i < 512; i += 256) s += g_s1_4[a * 512 + i];
    float m4 = block_reduce(s) * (1.0f / 512.0f);
    float glb4 = expf(-2.0f * m4);

    if (t == 0) out[a] = ds3 * glb3 + ds4 * glb4;
}

extern "C" void kernel_launch(void* const* d_in, const int* in_sizes, int n_in,
                              void* d_out, int out_size) {
    const float* r3 = (const float*)d_in[0];
    const float* d3 = (const float*)d_in[1];
    const float* r4 = (const float*)d_in[2];
    const float* d4 = (const float*)d_in[3];
    float* out = (float*)d_out;

    mean_kernel<3, 64 * 64><<<4 * 256, 256>>>(r3, d3);
    mean_kernel<4, 32 * 32><<<4 * 512, 256>>>(r4, d4);

    // layer3: 173056 pairs / 2 per warp = 86528 warps / 4 per block = 21632 blocks
    patch_kernel<3, 256, 64, 64, 13, 13, 5><<<21632, 128>>>(r3, d3);
    // layer4: 51200 pairs / 2 = 25600 warps / 4 = 6400 blocks
    patch_kernel<4, 512, 32, 32, 5, 5, 5><<<6400, 128>>>(r4, d4);

    final_kernel<<<4, 256>>>(out);
}

// round 7
// speedup vs baseline: 11.0189x; 1.2056x over previous
#include <cuda_runtime.h>
#include <math.h>

#define FULL 0xffffffffu
typedef unsigned long long ull;

// Deterministic scratch (no device-side allocation allowed).
__device__ float g_ds3[4 * 256 * 169];
__device__ float g_ds4[4 * 512 * 25];
__device__ float g_s1_3[4 * 256];
__device__ float g_s1_4[4 * 512];

// Round-robin (circle method) schedule: 15 rounds x 8 disjoint position-pairs.
// Position k holds column rr_idx(rd, k); position 0 pinned to column 0.
__host__ __device__ constexpr int rr_idx(int r, int k) {
    return (k == 0) ? 0 : ((k - 1 + r) % 15) + 1;
}

// ---- packed f32x2 helpers (sm_103a FFMA2/FMUL2) ----
__device__ __forceinline__ ull mul2(ull a, ull b) {
    ull d; asm("mul.rn.f32x2 %0, %1, %2;" : "=l"(d) : "l"(a), "l"(b)); return d;
}
__device__ __forceinline__ ull fma2(ull a, ull b, ull c) {
    ull d; asm("fma.rn.f32x2 %0, %1, %2, %3;" : "=l"(d) : "l"(a), "l"(b), "l"(c)); return d;
}
__device__ __forceinline__ ull pack2(float lo, float hi) {
    ull d; asm("mov.b64 %0, {%1, %2};" : "=l"(d) : "f"(lo), "f"(hi)); return d;
}
__device__ __forceinline__ void unpack2(float& lo, float& hi, ull v) {
    asm("mov.b64 {%0, %1}, %2;" : "=f"(lo), "=f"(hi) : "l"(v));
}

// ---------------------------------------------------------------------------
// Patch kernel: one warp = FOUR patch-pairs (8 matrices of 16x16).
//   group g = lane>>2 (matrix); within group lane m = lane&3 owns rows
//   m, m+4 (packed vP[16]) and m+8, m+12 (packed vQ[16]).
// One-sided Jacobi, static round-robin schedule:
//   - Gram products: packed FMA per lane, 2-level transposing butterfly over
//     the 4 group lanes -> lane m holds apq for pairs m and m+4.
//   - Lane m holds squared norms of positions (m,15-m) and (m+4,11-m):
//     both its pairs' angles are computed locally (2 angles/lane/round).
//   - cc, ss, -ss broadcast (static sources); rotations applied as packed
//     f32x2 FMAs to both packed row-pairs.
//   - Circle permutation of norms: 4 static shuffles + selects.
// ---------------------------------------------------------------------------
template <int LAYER, int C, int H, int W, int NH, int NW, int NSWEEP>
__global__ __launch_bounds__(128, 4) void patch_kernel(const float* __restrict__ ref,
                                                       const float* __restrict__ dist) {
    constexpr int NP = NH * NW;
    const int warpId = (blockIdx.x * blockDim.x + threadIdx.x) >> 5;
    const int lane = threadIdx.x & 31;
    const int g = lane >> 2;       // matrix group 0..7
    const int m = lane & 3;        // lane-in-group
    const int gb = lane & 28;      // group base lane
    const int sub = g & 1;         // 0 = ref, 1 = dist
    const int prl = g >> 1;        // patch-pair 0..3 within warp

    float* ds_out = (LAYER == 3) ? g_ds3 : g_ds4;

    const int pairIdx = warpId * 4 + prl;
    int a = pairIdx / (C * NP);
    int rem = pairIdx - a * (C * NP);
    int b = rem / NP;
    int p = rem - b * NP;
    int ph = p / NW;
    int pw = p - ph * NW;

    const float* src = sub ? dist : ref;
    const float* base = src + (((size_t)(a * C + b)) * H + (size_t)(ph * 4)) * W + (pw * 4);

    // vP[c] packs rows (m, m+4) of column c; vQ[c] packs rows (m+8, m+12).
    ull vP[16], vQ[16];
#pragma unroll
    for (int c = 0; c < 16; c++) {
        const float* col = base + (size_t)c * W;
        vP[c] = pack2(col[m], col[m + 4]);
        vQ[c] = pack2(col[m + 8], col[m + 12]);
    }

    // ---- initial squared column norms -> lane m gets n[m+4t], t=0..3 ----
    float dp0, dq0, dp1, dq1;
    {
        float acc[16];
#pragma unroll
        for (int j = 0; j < 16; j++) {
            ull t = fma2(vQ[j], vQ[j], mul2(vP[j], vP[j]));
            float lo, hi; unpack2(lo, hi, t);
            acc[j] = lo + hi;
        }
        float a8[8];
#pragma unroll
        for (int t = 0; t < 8; t++) {
            bool hi = (lane & 1);
            float send = hi ? acc[2 * t] : acc[2 * t + 1];
            float recv = __shfl_xor_sync(FULL, send, 1);
            a8[t] = (hi ? acc[2 * t + 1] : acc[2 * t]) + recv;
        }
        float e4[4];
#pragma unroll
        for (int t = 0; t < 4; t++) {
            bool hi = (lane & 2);
            float send = hi ? a8[2 * t] : a8[2 * t + 1];
            float recv = __shfl_xor_sync(FULL, send, 2);
            e4[t] = (hi ? a8[2 * t + 1] : a8[2 * t]) + recv;
        }
        dp0 = e4[0];                               // n[m]      (position m, rd=0)
        dp1 = e4[1];                               // n[m+4]    (position m+4)
        dq0 = __shfl_xor_sync(FULL, e4[3], 3);     // n[15-m]   (position 15-m)
        dq1 = __shfl_xor_sync(FULL, e4[2], 3);     // n[11-m]   (position 11-m)
    }

    // ---- Jacobi sweeps ----
#pragma unroll 1
    for (int sw = 0; sw < NSWEEP; sw++) {
#pragma unroll
        for (int rd = 0; rd < 15; rd++) {
            // Gram products of the 8 position-pairs (4 rows each, packed).
            float prod[8];
#pragma unroll
            for (int k = 0; k < 8; k++) {
                const int pi = rr_idx(rd, k);
                const int qi = rr_idx(rd, 15 - k);
                ull t = fma2(vQ[pi], vQ[qi], mul2(vP[pi], vP[qi]));
                float lo, hi; unpack2(lo, hi, t);
                prod[k] = lo + hi;
            }
            // 2-level transposing reduce over 4 lanes: lane m -> apq_m, apq_{m+4}.
            float c4[4];
#pragma unroll
            for (int t = 0; t < 4; t++) {
                bool hi = (lane & 1);
                float send = hi ? prod[2 * t] : prod[2 * t + 1];
                float recv = __shfl_xor_sync(FULL, send, 1);
                c4[t] = (hi ? prod[2 * t + 1] : prod[2 * t]) + recv;
            }
            float apq0, apq1;
            {
                bool hi = (lane & 2);
                float send0 = hi ? c4[0] : c4[1];
                float recv0 = __shfl_xor_sync(FULL, send0, 2);
                apq0 = (hi ? c4[1] : c4[0]) + recv0;
                float send1 = hi ? c4[2] : c4[3];
                float recv1 = __shfl_xor_sync(FULL, send1, 2);
                apq1 = (hi ? c4[3] : c4[2]) + recv1;
            }

            // Two rotation angles (pairs m and m+4), inputs all local.
            float cc0, ss0, ns0, cc1, ss1, ns1;
            {
                float D = dq0 - dp0;
                float h2 = fmaf(D, D, 4.0f * apq0 * apq0);
                bool ok = (h2 > 1e-30f);
                float inv_h = rsqrtf(fmaxf(h2, 1e-37f));
                float c2a = fabsf(D) * inv_h;
                float s2a = 2.0f * apq0 * inv_h * copysignf(1.0f, D);
                float u = fmaf(0.5f, c2a, 0.5f);
                float inv_su = rsqrtf(u);
                float cc = u * inv_su;
                float ss = 0.5f * s2a * inv_su;
                float tq = ss * inv_su * apq0;
                cc0 = ok ? cc : 1.0f;
                ss0 = ok ? ss : 0.0f;
                tq = ok ? tq : 0.0f;
                ns0 = -ss0;
                dp0 -= tq;
                dq0 += tq;
            }
            {
                float D = dq1 - dp1;
                float h2 = fmaf(D, D, 4.0f * apq1 * apq1);
                bool ok = (h2 > 1e-30f);
                float inv_h = rsqrtf(fmaxf(h2, 1e-37f));
                float c2a = fabsf(D) * inv_h;
                float s2a = 2.0f * apq1 * inv_h * copysignf(1.0f, D);
                float u = fmaf(0.5f, c2a, 0.5f);
                float inv_su = rsqrtf(u);
                float cc = u * inv_su;
                float ss = 0.5f * s2a * inv_su;
                float tq = ss * inv_su * apq1;
                cc1 = ok ? cc : 1.0f;
                ss1 = ok ? ss : 0.0f;
                tq = ok ? tq : 0.0f;
                ns1 = -ss1;
                dp1 -= tq;
                dq1 += tq;
            }

            // Broadcast cc, ss, -ss for all 8 pairs (static sources).
            float ccs[8], sss[8], nss[8];
#pragma unroll
            for (int k = 0; k < 8; k++) {
                ccs[k] = __shfl_sync(FULL, (k < 4) ? cc0 : cc1, gb | (k & 3));
                sss[k] = __shfl_sync(FULL, (k < 4) ? ss0 : ss1, gb | (k & 3));
                nss[k] = __shfl_sync(FULL, (k < 4) ? ns0 : ns1, gb | (k & 3));
            }

            // Apply the 8 rotations to both packed row-pairs (f32x2 FMAs).
#pragma unroll
            for (int k = 0; k < 8; k++) {
                const int pi = rr_idx(rd, k);
                const int qi = rr_idx(rd, 15 - k);
                ull ccp = pack2(ccs[k], ccs[k]);
                ull ssp = pack2(sss[k], sss[k]);
                ull nsp = pack2(nss[k], nss[k]);
                ull p0 = vP[pi], q0 = vP[qi];
                vP[pi] = fma2(ccp, p0, mul2(nsp, q0));
                vP[qi] = fma2(ccp, q0, mul2(ssp, p0));
                ull p1 = vQ[pi], q1 = vQ[qi];
                vQ[pi] = fma2(ccp, p1, mul2(nsp, q1));
                vQ[qi] = fma2(ccp, q1, mul2(ssp, p1));
            }

            // Circle-permute norms: n_new[k] = n_old[k+1] (k=1..14, wrap 15->1).
            {
                float t_dp0 = __shfl_sync(FULL, dp0, gb | ((m + 1) & 3));
                float t_dp1 = __shfl_sync(FULL, dp1, gb | ((m + 1) & 3));
                float t_dq0 = __shfl_sync(FULL, dq0, gb | ((m - 1) & 3));
                float t_dq1 = __shfl_sync(FULL, dq1, gb | ((m - 1) & 3));
                float ndp0 = (m == 0) ? dp0 : ((m == 3) ? t_dp1 : t_dp0);
                float ndp1 = (m == 3) ? dq1 : t_dp1;
                float ndq0 = (m == 0) ? t_dp0 : t_dq0;
                float ndq1 = (m == 0) ? t_dq0 : t_dq1;
                dp0 = ndp0; dp1 = ndp1; dq0 = ndq0; dq1 = ndq1;
            }
        }
    }
    // NSWEEP*15 rounds => position permutation is identity again.

    // ---- exact final column norms: lane m -> n[m+4t] ----
    float s4[4];
    {
        float acc[16];
#pragma unroll
        for (int j = 0; j < 16; j++) {
            ull t = fma2(vQ[j], vQ[j], mul2(vP[j], vP[j]));
            float lo, hi; unpack2(lo, hi, t);
            acc[j] = lo + hi;
        }
        float a8[8];
#pragma unroll
        for (int t = 0; t < 8; t++) {
            bool hi = (lane & 1);
            float send = hi ? acc[2 * t] : acc[2 * t + 1];
            float recv = __shfl_xor_sync(FULL, send, 1);
            a8[t] = (hi ? acc[2 * t + 1] : acc[2 * t]) + recv;
        }
#pragma unroll
        for (int t = 0; t < 4; t++) {
            bool hi = (lane & 2);
            float send = hi ? a8[2 * t] : a8[2 * t + 1];
            float recv = __shfl_xor_sync(FULL, send, 2);
            float e = (hi ? a8[2 * t + 1] : a8[2 * t]) + recv;
            s4[t] = sqrtf(fmaxf(e, 0.0f));        // sigma of column m+4t
        }
    }

    // ---- epilogue via shared memory (per warp: 8 matrices) ----
    __shared__ float sig[4][8][16];
    __shared__ float sigS[4][8][16];
    __shared__ float isg[4][8][16];
    __shared__ int rnk[4][8][16];
    __shared__ float Ush[4][8][16][16];   // [warp][group][sorted_col][row]
    const int wl = threadIdx.x >> 5;

#pragma unroll
    for (int t = 0; t < 4; t++) sig[wl][g][m + 4 * t] = s4[t];
    __syncwarp();

    // descending ranks (ties by column index) for this lane's 4 columns
    {
        float sv[16];
#pragma unroll
        for (int k = 0; k < 16; k++) sv[k] = sig[wl][g][k];
#pragma unroll
        for (int t = 0; t < 4; t++) {
            int j = m + 4 * t;
            float sj = s4[t];
            int rk = 0;
#pragma unroll
            for (int k = 0; k < 16; k++)
                rk += (int)((sv[k] > sj) || (sv[k] == sj && k < j));
            rnk[wl][g][j] = rk;
            isg[wl][g][j] = __fdividef(1.0f, sj + 1e-30f);
            sigS[wl][g][rk] = sj;
        }
    }
    __syncwarp();

    // stage sorted, normalized U (this lane owns rows m, m+4, m+8, m+12)
#pragma unroll
    for (int j = 0; j < 16; j++) {
        int rj = rnk[wl][g][j];
        float iv = isg[wl][g][j];
        float w0, w1, w2, w3;
        unpack2(w0, w1, vP[j]);
        unpack2(w2, w3, vQ[j]);
        Ush[wl][g][rj][m] = w0 * iv;
        Ush[wl][g][rj][m + 4] = w1 * iv;
        Ush[wl][g][rj][m + 8] = w2 * iv;
        Ush[wl][g][rj][m + 12] = w3 * iv;
    }
    __syncwarp();

    // combine ref/dist: 4 pairs x 16 rows over 32 lanes -> 2 tasks per lane
    const int row = lane & 15;
    const int hp = lane >> 4;             // 0 or 1
    float sd[2], su[2], sq2[2];
#pragma unroll
    for (int t = 0; t < 2; t++) {
        int pair = 2 * t + hp;            // t0: pairs 0/1, t1: pairs 2/3
        float urd = 0.0f;
#pragma unroll
        for (int i = 0; i < 16; i++)
            urd += fabsf(Ush[wl][2 * pair][i][row] * Ush[wl][2 * pair + 1][i][row]);
        float dd = sigS[wl][2 * pair][row] - sigS[wl][2 * pair + 1][row];
        sd[t] = dd * dd;
        su[t] = urd;
        sq2[t] = urd * urd;
    }
#pragma unroll
    for (int o = 1; o < 16; o <<= 1) {
#pragma unroll
        for (int t = 0; t < 2; t++) {
            sd[t] += __shfl_xor_sync(FULL, sd[t], o);
            su[t] += __shfl_xor_sync(FULL, su[t], o);
            sq2[t] += __shfl_xor_sync(FULL, sq2[t], o);
        }
    }
    if (row == 0) {
#pragma unroll
        for (int t = 0; t < 2; t++) {
            int pair = 2 * t + hp;
            float mean = su[t] * (1.0f / 16.0f);
            float var = (sq2[t] - su[t] * su[t] * (1.0f / 16.0f)) * (1.0f / 15.0f);
            float wt = sqrtf(fmaxf(var, 0.0f)) * __fdividef(1.0f, mean + 1e-9f);
            ds_out[warpId * 4 + pair] = sd[t] * wt;
        }
    }
}

// ---------------------------------------------------------------------------
// Per-channel global means -> s1 term.
// ---------------------------------------------------------------------------
template <int LAYER, int HW>
__global__ __launch_bounds__(256) void mean_kernel(const float* __restrict__ ref,
                                                   const float* __restrict__ dist) {
    float* s1out = (LAYER == 3) ? g_s1_3 : g_s1_4;
    const int ac = blockIdx.x;
    const float* rp = ref + (size_t)ac * HW;
    const float* dp = dist + (size_t)ac * HW;
    float sr = 0.0f, sdd = 0.0f;
    for (int i = threadIdx.x; i < HW; i += 256) {
        sr += rp[i];
        sdd += dp[i];
    }
    __shared__ float shr[256], shd[256];
    shr[threadIdx.x] = sr;
    shd[threadIdx.x] = sdd;
    __syncthreads();
    for (int o = 128; o > 0; o >>= 1) {
        if (threadIdx.x < o) {
            shr[threadIdx.x] += shr[threadIdx.x + o];
            shd[threadIdx.x] += shd[threadIdx.x + o];
        }
        __syncthreads();
    }
    if (threadIdx.x == 0) {
        float ym = shr[0] * (1.0f / HW);   // ref mean
        float xm = shd[0] * (1.0f / HW);   // dist mean
        float s1 = (2.0f * xm * ym + 1e-6f) / (xm * xm + ym * ym + 1e-6f);
        s1out[ac] = s1;
    }
}

// ---------------------------------------------------------------------------
// Final deterministic reduction: block a computes out[a].
// ---------------------------------------------------------------------------
__global__ __launch_bounds__(256) void final_kernel(float* __restrict__ out) {
    const int a = blockIdx.x;
    const int t = threadIdx.x;
    __shared__ float sh[256];

    auto block_reduce = [&](float vloc) -> float {
        sh[t] = vloc;
        __syncthreads();
        for (int o = 128; o > 0; o >>= 1) {
            if (t < o) sh[t] += sh[t + o];
            __syncthreads();
        }
        float res = sh[0];
        __syncthreads();
        return res;
    };

    float s = 0.0f;
    for (int i = t; i < 256 * 169; i += 256) s += g_ds3[a * 256 * 169 + i];
    float ds3 = block_reduce(s) * (1.0f / (256.0f * 169.0f));

    float m3 = block_reduce(g_s1_3[a * 256 + t]) * (1.0f / 256.0f);
    float glb3 = expf(-2.0f * m3);

    s = 0.0f;
    for (int i = t; i < 512 * 25; i += 256) s += g_ds4[a * 512 * 25 + i];
    float ds4 = block_reduce(s) * (1.0f / (512.0f * 25.0f));

    s = 0.0f;
    for (int i = t; i < 512; i += 256) s += g_s1_4[a * 512 + i];
    float m4 = block_reduce(s) * (1.0f / 512.0f);
    float glb4 = expf(-2.0f * m4);

    if (t == 0) out[a] = ds3 * glb3 + ds4 * glb4;
}

extern "C" void kernel_launch(void* const* d_in, const int* in_sizes, int n_in,
                              void* d_out, int out_size) {
    const float* r3 = (const float*)d_in[0];
    const float* d3 = (const float*)d_in[1];
    const float* r4 = (const float*)d_in[2];
    const float* d4 = (const float*)d_in[3];
    float* out = (float*)d_out;

    mean_kernel<3, 64 * 64><<<4 * 256, 256>>>(r3, d3);
    mean_kernel<4, 32 * 32><<<4 * 512, 256>>>(r4, d4);

    // layer3: 173056 pairs / 4 per warp = 43264 warps / 4 per block = 10816 blocks
    patch_kernel<3, 256, 64, 64, 13, 13, 5><<<10816, 128>>>(r3, d3);
    // layer4: 51200 pairs / 4 = 12800 warps / 4 = 3200 blocks
    patch_kernel<4, 512, 32, 32, 5, 5, 5><<<3200, 128>>>(r4, d4);

    final_kernel<<<4, 256>>>(out);
}

// round 8
// speedup vs baseline: 11.4131x; 1.0358x over previous
#include <cuda_runtime.h>
#include <math.h>

#define FULL 0xffffffffu
typedef unsigned long long ull;

// Deterministic scratch (no device-side allocation allowed).
__device__ float g_ds3[4 * 256 * 169];
__device__ float g_ds4[4 * 512 * 25];
__device__ float g_s1_3[4 * 256];
__device__ float g_s1_4[4 * 512];

// Round-robin (circle method) schedule: 15 rounds x 8 disjoint position-pairs.
// Position k holds column rr_idx(rd, k); position 0 pinned to column 0.
__host__ __device__ constexpr int rr_idx(int r, int k) {
    return (k == 0) ? 0 : ((k - 1 + r) % 15) + 1;
}

// ---- packed f32x2 helpers (sm_103a FFMA2/FMUL2) ----
__device__ __forceinline__ ull mul2(ull a, ull b) {
    ull d; asm("mul.rn.f32x2 %0, %1, %2;" : "=l"(d) : "l"(a), "l"(b)); return d;
}
__device__ __forceinline__ ull fma2(ull a, ull b, ull c) {
    ull d; asm("fma.rn.f32x2 %0, %1, %2, %3;" : "=l"(d) : "l"(a), "l"(b), "l"(c)); return d;
}
__device__ __forceinline__ ull pack2(float lo, float hi) {
    ull d; asm("mov.b64 %0, {%1, %2};" : "=l"(d) : "f"(lo), "f"(hi)); return d;
}
__device__ __forceinline__ void unpack2(float& lo, float& hi, ull v) {
    asm("mov.b64 {%0, %1}, %2;" : "=f"(lo), "=f"(hi) : "l"(v));
}

// ---------------------------------------------------------------------------
// Patch kernel: one warp = FOUR patch-pairs (8 matrices of 16x16).
//   group g = lane>>2 (matrix); within group lane m = lane&3 owns rows
//   m, m+4 (packed vP[16]) and m+8, m+12 (packed vQ[16]).
// One-sided Jacobi, static round-robin schedule. Broadcast interleaved with
// rotation (low register pressure); -ss derived locally by sign-flip XOR.
// ---------------------------------------------------------------------------
template <int LAYER, int C, int H, int W, int NH, int NW, int NSWEEP>
__global__ __launch_bounds__(128, 5) void patch_kernel(const float* __restrict__ ref,
                                                       const float* __restrict__ dist) {
    constexpr int NP = NH * NW;
    const int warpId = (blockIdx.x * blockDim.x + threadIdx.x) >> 5;
    const int lane = threadIdx.x & 31;
    const int g = lane >> 2;       // matrix group 0..7
    const int m = lane & 3;        // lane-in-group
    const int gb = lane & 28;      // group base lane
    const int sub = g & 1;         // 0 = ref, 1 = dist
    const int prl = g >> 1;        // patch-pair 0..3 within warp

    float* ds_out = (LAYER == 3) ? g_ds3 : g_ds4;

    const int pairIdx = warpId * 4 + prl;
    int a = pairIdx / (C * NP);
    int rem = pairIdx - a * (C * NP);
    int b = rem / NP;
    int p = rem - b * NP;
    int ph = p / NW;
    int pw = p - ph * NW;

    const float* src = sub ? dist : ref;
    const float* base = src + (((size_t)(a * C + b)) * H + (size_t)(ph * 4)) * W + (pw * 4);

    // vP[c] packs rows (m, m+4) of column c; vQ[c] packs rows (m+8, m+12).
    ull vP[16], vQ[16];
#pragma unroll
    for (int c = 0; c < 16; c++) {
        const float* col = base + (size_t)c * W;
        vP[c] = pack2(col[m], col[m + 4]);
        vQ[c] = pack2(col[m + 8], col[m + 12]);
    }

    // ---- initial squared column norms -> lane m gets n[m+4t], t=0..3 ----
    float dp0, dq0, dp1, dq1;
    {
        float acc[16];
#pragma unroll
        for (int j = 0; j < 16; j++) {
            ull t = fma2(vQ[j], vQ[j], mul2(vP[j], vP[j]));
            float lo, hi; unpack2(lo, hi, t);
            acc[j] = lo + hi;
        }
        float a8[8];
#pragma unroll
        for (int t = 0; t < 8; t++) {
            bool hi = (lane & 1);
            float send = hi ? acc[2 * t] : acc[2 * t + 1];
            float recv = __shfl_xor_sync(FULL, send, 1);
            a8[t] = (hi ? acc[2 * t + 1] : acc[2 * t]) + recv;
        }
        float e4[4];
#pragma unroll
        for (int t = 0; t < 4; t++) {
            bool hi = (lane & 2);
            float send = hi ? a8[2 * t] : a8[2 * t + 1];
            float recv = __shfl_xor_sync(FULL, send, 2);
            e4[t] = (hi ? a8[2 * t + 1] : a8[2 * t]) + recv;
        }
        dp0 = e4[0];                               // n[m]      (position m, rd=0)
        dp1 = e4[1];                               // n[m+4]    (position m+4)
        dq0 = __shfl_xor_sync(FULL, e4[3], 3);     // n[15-m]   (position 15-m)
        dq1 = __shfl_xor_sync(FULL, e4[2], 3);     // n[11-m]   (position 11-m)
    }

    // ---- Jacobi sweeps ----
#pragma unroll 1
    for (int sw = 0; sw < NSWEEP; sw++) {
#pragma unroll
        for (int rd = 0; rd < 15; rd++) {
            // Gram products of the 8 position-pairs (4 rows each, packed).
            float prod[8];
#pragma unroll
            for (int k = 0; k < 8; k++) {
                const int pi = rr_idx(rd, k);
                const int qi = rr_idx(rd, 15 - k);
                ull t = fma2(vQ[pi], vQ[qi], mul2(vP[pi], vP[qi]));
                float lo, hi; unpack2(lo, hi, t);
                prod[k] = lo + hi;
            }
            // 2-level transposing reduce over 4 lanes: lane m -> apq_m, apq_{m+4}.
            float c4[4];
#pragma unroll
            for (int t = 0; t < 4; t++) {
                bool hi = (lane & 1);
                float send = hi ? prod[2 * t] : prod[2 * t + 1];
                float recv = __shfl_xor_sync(FULL, send, 1);
                c4[t] = (hi ? prod[2 * t + 1] : prod[2 * t]) + recv;
            }
            float apq0, apq1;
            {
                bool hi = (lane & 2);
                float send0 = hi ? c4[0] : c4[1];
                float recv0 = __shfl_xor_sync(FULL, send0, 2);
                apq0 = (hi ? c4[1] : c4[0]) + recv0;
                float send1 = hi ? c4[2] : c4[3];
                float recv1 = __shfl_xor_sync(FULL, send1, 2);
                apq1 = (hi ? c4[3] : c4[2]) + recv1;
            }

            // Two rotation angles (pairs m and m+4), inputs all local.
            float cc0, ss0, cc1, ss1;
            {
                float D = dq0 - dp0;
                float h2 = fmaf(D, D, 4.0f * apq0 * apq0);
                bool ok = (h2 > 1e-30f);
                float inv_h = rsqrtf(fmaxf(h2, 1e-37f));
                float c2a = fabsf(D) * inv_h;
                float s2a = 2.0f * apq0 * inv_h * copysignf(1.0f, D);
                float u = fmaf(0.5f, c2a, 0.5f);
                float inv_su = rsqrtf(u);
                float cc = u * inv_su;
                float ss = 0.5f * s2a * inv_su;
                float tq = ss * inv_su * apq0;
                cc0 = ok ? cc : 1.0f;
                ss0 = ok ? ss : 0.0f;
                tq = ok ? tq : 0.0f;
                dp0 -= tq;
                dq0 += tq;
            }
            {
                float D = dq1 - dp1;
                float h2 = fmaf(D, D, 4.0f * apq1 * apq1);
                bool ok = (h2 > 1e-30f);
                float inv_h = rsqrtf(fmaxf(h2, 1e-37f));
                float c2a = fabsf(D) * inv_h;
                float s2a = 2.0f * apq1 * inv_h * copysignf(1.0f, D);
                float u = fmaf(0.5f, c2a, 0.5f);
                float inv_su = rsqrtf(u);
                float cc = u * inv_su;
                float ss = 0.5f * s2a * inv_su;
                float tq = ss * inv_su * apq1;
                cc1 = ok ? cc : 1.0f;
                ss1 = ok ? ss : 0.0f;
                tq = ok ? tq : 0.0f;
                dp1 -= tq;
                dq1 += tq;
            }

            // Broadcast + rotate, interleaved per pair (low register pressure).
            // -ss derived locally: XOR sign bits of both packed halves.
#pragma unroll
            for (int k = 0; k < 8; k++) {
                const int pi = rr_idx(rd, k);
                const int qi = rr_idx(rd, 15 - k);
                float cck = __shfl_sync(FULL, (k < 4) ? cc0 : cc1, gb | (k & 3));
                float ssk = __shfl_sync(FULL, (k < 4) ? ss0 : ss1, gb | (k & 3));
                ull ccp = pack2(cck, cck);
                ull ssp = pack2(ssk, ssk);
                ull nsp = ssp ^ 0x8000000080000000ULL;
                ull p0 = vP[pi], q0 = vP[qi];
                vP[pi] = fma2(ccp, p0, mul2(nsp, q0));
                vP[qi] = fma2(ccp, q0, mul2(ssp, p0));
                ull p1 = vQ[pi], q1 = vQ[qi];
                vQ[pi] = fma2(ccp, p1, mul2(nsp, q1));
                vQ[qi] = fma2(ccp, q1, mul2(ssp, p1));
            }

            // Circle-permute norms: n_new[k] = n_old[k+1] (k=1..14, wrap 15->1).
            {
                float t_dp0 = __shfl_sync(FULL, dp0, gb | ((m + 1) & 3));
                float t_dp1 = __shfl_sync(FULL, dp1, gb | ((m + 1) & 3));
                float t_dq0 = __shfl_sync(FULL, dq0, gb | ((m - 1) & 3));
                float t_dq1 = __shfl_sync(FULL, dq1, gb | ((m - 1) & 3));
                float ndp0 = (m == 0) ? dp0 : ((m == 3) ? t_dp1 : t_dp0);
                float ndp1 = (m == 3) ? dq1 : t_dp1;
                float ndq0 = (m == 0) ? t_dp0 : t_dq0;
                float ndq1 = (m == 0) ? t_dq0 : t_dq1;
                dp0 = ndp0; dp1 = ndp1; dq0 = ndq0; dq1 = ndq1;
            }
        }
    }
    // NSWEEP*15 rounds => position permutation is identity again.

    // ---- exact final column norms: lane m -> n[m+4t] ----
    float s4[4];
    {
        float acc[16];
#pragma unroll
        for (int j = 0; j < 16; j++) {
            ull t = fma2(vQ[j], vQ[j], mul2(vP[j], vP[j]));
            float lo, hi; unpack2(lo, hi, t);
            acc[j] = lo + hi;
        }
        float a8[8];
#pragma unroll
        for (int t = 0; t < 8; t++) {
            bool hi = (lane & 1);
            float send = hi ? acc[2 * t] : acc[2 * t + 1];
            float recv = __shfl_xor_sync(FULL, send, 1);
            a8[t] = (hi ? acc[2 * t + 1] : acc[2 * t]) + recv;
        }
#pragma unroll
        for (int t = 0; t < 4; t++) {
            bool hi = (lane & 2);
            float send = hi ? a8[2 * t] : a8[2 * t + 1];
            float recv = __shfl_xor_sync(FULL, send, 2);
            float e = (hi ? a8[2 * t + 1] : a8[2 * t]) + recv;
            s4[t] = sqrtf(fmaxf(e, 0.0f));        // sigma of column m+4t
        }
    }

    // ---- epilogue via shared memory (per warp: 8 matrices) ----
    __shared__ float sig[4][8][16];
    __shared__ float sigS[4][8][16];
    __shared__ float isg[4][8][16];
    __shared__ int rnk[4][8][16];
    __shared__ float Ush[4][8][16][16];   // [warp][group][sorted_col][row]
    const int wl = threadIdx.x >> 5;

#pragma unroll
    for (int t = 0; t < 4; t++) sig[wl][g][m + 4 * t] = s4[t];
    __syncwarp();

    // descending ranks (ties by column index) for this lane's 4 columns
    {
        float sv[16];
#pragma unroll
        for (int k = 0; k < 16; k++) sv[k] = sig[wl][g][k];
#pragma unroll
        for (int t = 0; t < 4; t++) {
            int j = m + 4 * t;
            float sj = s4[t];
            int rk = 0;
#pragma unroll
            for (int k = 0; k < 16; k++)
                rk += (int)((sv[k] > sj) || (sv[k] == sj && k < j));
            rnk[wl][g][j] = rk;
            isg[wl][g][j] = __fdividef(1.0f, sj + 1e-30f);
            sigS[wl][g][rk] = sj;
        }
    }
    __syncwarp();

    // stage sorted, normalized U (this lane owns rows m, m+4, m+8, m+12)
#pragma unroll
    for (int j = 0; j < 16; j++) {
        int rj = rnk[wl][g][j];
        float iv = isg[wl][g][j];
        float w0, w1, w2, w3;
        unpack2(w0, w1, vP[j]);
        unpack2(w2, w3, vQ[j]);
        Ush[wl][g][rj][m] = w0 * iv;
        Ush[wl][g][rj][m + 4] = w1 * iv;
        Ush[wl][g][rj][m + 8] = w2 * iv;
        Ush[wl][g][rj][m + 12] = w3 * iv;
    }
    __syncwarp();

    // combine ref/dist: 4 pairs x 16 rows over 32 lanes -> 2 tasks per lane
    const int row = lane & 15;
    const int hp = lane >> 4;             // 0 or 1
    float sd[2], su[2], sq2[2];
#pragma unroll
    for (int t = 0; t < 2; t++) {
        int pair = 2 * t + hp;            // t0: pairs 0/1, t1: pairs 2/3
        float urd = 0.0f;
#pragma unroll
        for (int i = 0; i < 16; i++)
            urd += fabsf(Ush[wl][2 * pair][i][row] * Ush[wl][2 * pair + 1][i][row]);
        float dd = sigS[wl][2 * pair][row] - sigS[wl][2 * pair + 1][row];
        sd[t] = dd * dd;
        su[t] = urd;
        sq2[t] = urd * urd;
    }
#pragma unroll
    for (int o = 1; o < 16; o <<= 1) {
#pragma unroll
        for (int t = 0; t < 2; t++) {
            sd[t] += __shfl_xor_sync(FULL, sd[t], o);
            su[t] += __shfl_xor_sync(FULL, su[t], o);
            sq2[t] += __shfl_xor_sync(FULL, sq2[t], o);
        }
    }
    if (row == 0) {
#pragma unroll
        for (int t = 0; t < 2; t++) {
            int pair = 2 * t + hp;
            float mean = su[t] * (1.0f / 16.0f);
            float var = (sq2[t] - su[t] * su[t] * (1.0f / 16.0f)) * (1.0f / 15.0f);
            float wt = sqrtf(fmaxf(var, 0.0f)) * __fdividef(1.0f, mean + 1e-9f);
            ds_out[warpId * 4 + pair] = sd[t] * wt;
        }
    }
}

// ---------------------------------------------------------------------------
// Per-channel global means -> s1 term.
// ---------------------------------------------------------------------------
template <int LAYER, int HW>
__global__ __launch_bounds__(256) void mean_kernel(const float* __restrict__ ref,
                                                   const float* __restrict__ dist) {
    float* s1out = (LAYER == 3) ? g_s1_3 : g_s1_4;
    const int ac = blockIdx.x;
    const float* rp = ref + (size_t)ac * HW;
    const float* dp = dist + (size_t)ac * HW;
    float sr = 0.0f, sdd = 0.0f;
    for (int i = threadIdx.x; i < HW; i += 256) {
        sr += rp[i];
        sdd += dp[i];
    }
    __shared__ float shr[256], shd[256];
    shr[threadIdx.x] = sr;
    shd[threadIdx.x] = sdd;
    __syncthreads();
    for (int o = 128; o > 0; o >>= 1) {
        if (threadIdx.x < o) {
            shr[threadIdx.x] += shr[threadIdx.x + o];
            shd[threadIdx.x] += shd[threadIdx.x + o];
        }
        __syncthreads();
    }
    if (threadIdx.x == 0) {
        float ym = shr[0] * (1.0f / HW);   // ref mean
        float xm = shd[0] * (1.0f / HW);   // dist mean
        float s1 = (2.0f * xm * ym + 1e-6f) / (xm * xm + ym * ym + 1e-6f);
        s1out[ac] = s1;
    }
}

// ---------------------------------------------------------------------------
// Final deterministic reduction: block a computes out[a].
// ---------------------------------------------------------------------------
__global__ __launch_bounds__(256) void final_kernel(float* __restrict__ out) {
    const int a = blockIdx.x;
    const int t = threadIdx.x;
    __shared__ float sh[256];

    auto block_reduce = [&](float vloc) -> float {
        sh[t] = vloc;
        __syncthreads();
        for (int o = 128; o > 0; o >>= 1) {
            if (t < o) sh[t] += sh[t + o];
            __syncthreads();
        }
        float res = sh[0];
        __syncthreads();
        return res;
    };

    float s = 0.0f;
    for (int i = t; i < 256 * 169; i += 256) s += g_ds3[a * 256 * 169 + i];
    float ds3 = block_reduce(s) * (1.0f / (256.0f * 169.0f));

    float m3 = block_reduce(g_s1_3[a * 256 + t]) * (1.0f / 256.0f);
    float glb3 = expf(-2.0f * m3);

    s = 0.0f;
    for (int i = t; i < 512 * 25; i += 256) s += g_ds4[a * 512 * 25 + i];
    float ds4 = block_reduce(s) * (1.0f / (512.0f * 25.0f));

    s = 0.0f;
    for (int i = t; i < 512; i += 256) s += g_s1_4[a * 512 + i];
    float m4 = block_reduce(s) * (1.0f / 512.0f);
    float glb4 = expf(-2.0f * m4);

    if (t == 0) out[a] = ds3 * glb3 + ds4 * glb4;
}

extern "C" void kernel_launch(void* const* d_in, const int* in_sizes, int n_in,
                              void* d_out, int out_size) {
    const float* r3 = (const float*)d_in[0];
    const float* d3 = (const float*)d_in[1];
    const float* r4 = (const float*)d_in[2];
    const float* d4 = (const float*)d_in[3];
    float* out = (float*)d_out;

    mean_kernel<3, 64 * 64><<<4 * 256, 256>>>(r3, d3);
    mean_kernel<4, 32 * 32><<<4 * 512, 256>>>(r4, d4);

    // layer3: 173056 pairs / 4 per warp = 43264 warps / 4 per block = 10816 blocks
    patch_kernel<3, 256, 64, 64, 13, 13, 5><<<10816, 128>>>(r3, d3);
    // layer4: 51200 pairs / 4 = 12800 warps / 4 = 3200 blocks
    patch_kernel<4, 512, 32, 32, 5, 5, 5><<<3200, 128>>>(r4, d4);

    final_kernel<<<4, 256>>>(out);
}